// round 1
// baseline (speedup 1.0000x reference)
#include <cuda_runtime.h>

// db4 single-level 2D DWT, circular padding (end), stride-2 cross-correlation.
// x: (96, 512, 512) f32 -> out: (96*4, 256, 256) f32, subband order ll,lh,hl,hh.

#define HH   512
#define WW   512
#define OHH  256
#define OWW  256
#define TH   32            // output tile rows per block
#define TW   32            // output tile cols per block
#define IN_H (2*TH + 6)    // 70 input rows needed (2h+t, t<8)
#define IN_W (2*TW + 6)    // 70 input cols needed
#define IN_PITCH 72        // pad pitch

__global__ __launch_bounds__(256) void dwt2d_db4_kernel(
    const float* __restrict__ x,
    const float* __restrict__ dec,   // (2,8): [0..7]=lo, [8..15]=hi
    float* __restrict__ out)
{
    __shared__ float s_in[IN_H][IN_PITCH];
    __shared__ float s_lo[IN_H][TW];
    __shared__ float s_hi[IN_H][TW];
    __shared__ float f_lo[8];
    __shared__ float f_hi[8];

    const int tid = threadIdx.x;
    if (tid < 8) {
        f_lo[tid] = dec[tid];
        f_hi[tid] = dec[8 + tid];
    }

    const int img = blockIdx.z;            // 0..95  (b*3 + c)
    const int h0  = blockIdx.y * TH;        // output row base
    const int w0  = blockIdx.x * TW;        // output col base
    const int r0  = 2 * h0;                 // input row base
    const int c0  = 2 * w0;                 // input col base

    const float* __restrict__ xin = x + (size_t)img * HH * WW;

    // ---- load 70x70 input tile with circular wrap ----
    #pragma unroll 4
    for (int idx = tid; idx < IN_H * IN_W; idx += 256) {
        int r = idx / IN_W;
        int c = idx - r * IN_W;
        int gr = (r0 + r) & (HH - 1);
        int gc = (c0 + c) & (WW - 1);
        s_in[r][c] = xin[(size_t)gr * WW + gc];
    }
    __syncthreads();

    // ---- row pass (along W): 70 rows x 32 output cols, lo & hi ----
    #pragma unroll 2
    for (int idx = tid; idx < IN_H * TW; idx += 256) {
        int r = idx / TW;
        int w = idx & (TW - 1);
        float lo = 0.f, hi = 0.f;
        #pragma unroll
        for (int t = 0; t < 8; t++) {
            float v = s_in[r][2 * w + t];
            lo = fmaf(f_lo[t], v, lo);
            hi = fmaf(f_hi[t], v, hi);
        }
        s_lo[r][w] = lo;
        s_hi[r][w] = hi;
    }
    __syncthreads();

    // ---- column pass (along H): 32x32 outputs, 4 subbands ----
    float* __restrict__ outi = out + (size_t)img * 4 * OHH * OWW;
    #pragma unroll
    for (int idx = tid; idx < TH * TW; idx += 256) {
        int h = idx / TW;
        int w = idx & (TW - 1);
        float ll = 0.f, lh = 0.f, hl = 0.f, hh = 0.f;
        #pragma unroll
        for (int t = 0; t < 8; t++) {
            float a = s_lo[2 * h + t][w];
            float b = s_hi[2 * h + t][w];
            ll = fmaf(f_lo[t], a, ll);
            lh = fmaf(f_hi[t], a, lh);
            hl = fmaf(f_lo[t], b, hl);
            hh = fmaf(f_hi[t], b, hh);
        }
        size_t o = (size_t)(h0 + h) * OWW + (w0 + w);
        outi[0 * (size_t)OHH * OWW + o] = ll;
        outi[1 * (size_t)OHH * OWW + o] = lh;
        outi[2 * (size_t)OHH * OWW + o] = hl;
        outi[3 * (size_t)OHH * OWW + o] = hh;
    }
}

extern "C" void kernel_launch(void* const* d_in, const int* in_sizes, int n_in,
                              void* d_out, int out_size)
{
    const float* x   = (const float*)d_in[0];   // (32,3,512,512) f32
    const float* dec = (const float*)d_in[1];   // (2,8) f32
    float* out = (float*)d_out;                 // (32,12,256,256) f32

    dim3 grid(OWW / TW, OHH / TH, 96);          // (8, 8, 96)
    dwt2d_db4_kernel<<<grid, 256>>>(x, dec, out);
}

// round 2
// speedup vs baseline: 1.5137x; 1.5137x over previous
#include <cuda_runtime.h>

// db4 single-level 2D DWT, circular padding (end), stride-2 cross-correlation.
// x: (96, 512, 512) f32 -> out: (96*4, 256, 256) f32, subband order ll,lh,hl,hh.

#define HH   512
#define WW   512
#define OWW  256
#define TH   32            // output tile rows per block
#define TW   32            // output tile cols per block
#define IN_H 70            // input rows needed (2*TH + 6)
#define NF4  18            // float4 loads per input row (72 cols, wrap-safe)
#define EP   36            // even/odd smem pitch (need cols 0..35)

// db4 analysis taps (identical fp32 literals to the reference)
#define FL0 (-0.010597401784997278f)
#define FL1 ( 0.032883011666982945f)
#define FL2 ( 0.030841381835986965f)
#define FL3 (-0.18703481171888114f)
#define FL4 (-0.02798376941698385f)
#define FL5 ( 0.6308807679295904f)
#define FL6 ( 0.7148465705525415f)
#define FL7 ( 0.23037781330885523f)
#define FH0 (-0.23037781330885523f)
#define FH1 ( 0.7148465705525415f)
#define FH2 (-0.6308807679295904f)
#define FH3 (-0.02798376941698385f)
#define FH4 ( 0.18703481171888114f)
#define FH5 ( 0.030841381835986965f)
#define FH6 (-0.032883011666982945f)
#define FH7 (-0.010597401784997278f)

__global__ __launch_bounds__(256) void dwt2d_db4_kernel(
    const float* __restrict__ x,
    float* __restrict__ out)
{
    // de-interleaved input tile: even/odd columns, stride-1 row-pass reads
    __shared__ __align__(16) float  s_even[IN_H][EP];
    __shared__ __align__(16) float  s_odd [IN_H][EP];
    // row-pass result: {lo, hi} packed per point
    __shared__ __align__(16) float2 s_lh  [IN_H][TW];

    const int tid = threadIdx.x;
    const int img = blockIdx.z;             // 0..95
    const int h0  = blockIdx.y * TH;        // output row base
    const int w0  = blockIdx.x * TW;        // output col base
    const int r0  = 2 * h0;
    const int c0  = 2 * w0;                 // multiple of 64 -> float4 aligned

    const float* __restrict__ xin = x + (size_t)img * HH * WW;

    // ---- load 70 rows x 72 cols as float4, split even/odd ----
    #pragma unroll
    for (int i = 0; i < 5; i++) {
        int idx = tid + i * 256;
        if (idx < IN_H * NF4) {
            int r = idx / NF4;
            int j = idx - r * NF4;
            int gr = (r0 + r) & (HH - 1);
            int gc = (c0 + 4 * j) & (WW - 1);   // stays multiple of 4 -> aligned
            float4 v = *(const float4*)(xin + (size_t)gr * WW + gc);
            *(float2*)&s_even[r][2 * j] = make_float2(v.x, v.z);
            *(float2*)&s_odd [r][2 * j] = make_float2(v.y, v.w);
        }
    }
    __syncthreads();

    // ---- row pass: 70 rows x 32 cols, conflict-free stride-1 reads ----
    #pragma unroll
    for (int i = 0; i < 9; i++) {
        int idx = tid + i * 256;
        if (idx < IN_H * TW) {
            int r = idx >> 5;
            int w = idx & 31;
            float e0 = s_even[r][w],     o0 = s_odd[r][w];
            float e1 = s_even[r][w + 1], o1 = s_odd[r][w + 1];
            float e2 = s_even[r][w + 2], o2 = s_odd[r][w + 2];
            float e3 = s_even[r][w + 3], o3 = s_odd[r][w + 3];
            float lo, hi;
            lo = FL0 * e0;            hi = FH0 * e0;
            lo = fmaf(FL1, o0, lo);   hi = fmaf(FH1, o0, hi);
            lo = fmaf(FL2, e1, lo);   hi = fmaf(FH2, e1, hi);
            lo = fmaf(FL3, o1, lo);   hi = fmaf(FH3, o1, hi);
            lo = fmaf(FL4, e2, lo);   hi = fmaf(FH4, e2, hi);
            lo = fmaf(FL5, o2, lo);   hi = fmaf(FH5, o2, hi);
            lo = fmaf(FL6, e3, lo);   hi = fmaf(FH6, e3, hi);
            lo = fmaf(FL7, o3, lo);   hi = fmaf(FH7, o3, hi);
            s_lh[r][w] = make_float2(lo, hi);
        }
    }
    __syncthreads();

    // ---- column pass: each thread does 2 adjacent output cols, 4 subbands ----
    float* __restrict__ outi = out + (size_t)img * 4 * OWW * OWW;
    #pragma unroll
    for (int i = 0; i < 2; i++) {
        int idx = tid + i * 256;             // 0..511
        int h  = idx >> 4;                   // 0..31
        int wp = idx & 15;                   // column pair index
        float ll0 = 0.f, lh0 = 0.f, hl0 = 0.f, hh0 = 0.f;
        float ll1 = 0.f, lh1 = 0.f, hl1 = 0.f, hh1 = 0.f;
        #pragma unroll
        for (int t = 0; t < 8; t++) {
            // v = {lo(c0), hi(c0), lo(c1), hi(c1)} for row 2h+t
            float4 v = *(const float4*)&s_lh[2 * h + t][2 * wp];
            float fl = (t==0?FL0:t==1?FL1:t==2?FL2:t==3?FL3:t==4?FL4:t==5?FL5:t==6?FL6:FL7);
            float fh = (t==0?FH0:t==1?FH1:t==2?FH2:t==3?FH3:t==4?FH4:t==5?FH5:t==6?FH6:FH7);
            ll0 = fmaf(fl, v.x, ll0);  lh0 = fmaf(fh, v.x, lh0);
            hl0 = fmaf(fl, v.y, hl0);  hh0 = fmaf(fh, v.y, hh0);
            ll1 = fmaf(fl, v.z, ll1);  lh1 = fmaf(fh, v.z, lh1);
            hl1 = fmaf(fl, v.w, hl1);  hh1 = fmaf(fh, v.w, hh1);
        }
        size_t o = (size_t)(h0 + h) * OWW + (w0 + 2 * wp);
        const size_t SB = (size_t)OWW * OWW;
        *(float2*)(outi + 0 * SB + o) = make_float2(ll0, ll1);
        *(float2*)(outi + 1 * SB + o) = make_float2(lh0, lh1);
        *(float2*)(outi + 2 * SB + o) = make_float2(hl0, hl1);
        *(float2*)(outi + 3 * SB + o) = make_float2(hh0, hh1);
    }
}

extern "C" void kernel_launch(void* const* d_in, const int* in_sizes, int n_in,
                              void* d_out, int out_size)
{
    const float* x = (const float*)d_in[0];   // (32,3,512,512) f32
    float* out = (float*)d_out;               // (32,12,256,256) f32

    dim3 grid(OWW / TW, OWW / TH, 96);        // (8, 8, 96)
    dwt2d_db4_kernel<<<grid, 256>>>(x, out);
}